// round 2
// baseline (speedup 1.0000x reference)
#include <cuda_runtime.h>
#include <cuda_bf16.h>
#include <cstdint>

// Problem constants: B=8, S=2048, H=512, G=2, V=320, D=256
#define MM 16384      // B*S
#define KK 512        // H
#define NN 640        // G*V
#define VV 320
#define DG 128        // D/G

#define GEMM_BM 128
#define GEMM_BN 128
#define GEMM_BK 16

// Scratch (static device globals: allocation-free)
__device__ float g_logits[(size_t)MM * NN];   // 40 MB
__device__ float g_marginal[NN];
__device__ float g_maskf[MM];
__device__ float g_msum;

// ---------------------------------------------------------------------------
// Init: zero marginal, detect mask dtype (int32 vs uint8), expand mask, sum it
// ---------------------------------------------------------------------------
__global__ void __launch_bounds__(1024) init_kernel(const void* __restrict__ maskraw) {
    int tid = threadIdx.x;
    if (tid < NN) g_marginal[tid] = 0.f;

    __shared__ int isU8;
    if (tid == 0) isU8 = 0;
    __syncthreads();

    const unsigned char* mb = (const unsigned char*)maskraw;
    int any = 0;
    for (int i = tid; i < MM; i += 1024)
        if ((i & 3) && mb[i]) any = 1;
    if (any) isU8 = 1;
    __syncthreads();

    bool u8 = (isU8 != 0);
    const int* mi = (const int*)maskraw;
    float local = 0.f;
    for (int i = tid; i < MM; i += 1024) {
        bool on = u8 ? (mb[i] != 0) : (mi[i] != 0);
        float v = on ? 1.f : 0.f;
        g_maskf[i] = v;
        local += v;
    }
    // block reduce (32 warps)
    __shared__ float red[32];
    for (int o = 16; o; o >>= 1) local += __shfl_xor_sync(0xffffffffu, local, o);
    if ((tid & 31) == 0) red[tid >> 5] = local;
    __syncthreads();
    if (tid < 32) {
        float s = red[tid];
        for (int o = 16; o; o >>= 1) s += __shfl_xor_sync(0xffffffffu, s, o);
        if (tid == 0) g_msum = s;
    }
}

// ---------------------------------------------------------------------------
// FP32 SGEMM: logits[MM,NN] = hidden[MM,KK] @ W[KK,NN] + bias
// 128x128x16 block tile, 256 threads, 8x8 per-thread microtile.
// Global loads for tile k+1 are issued before the barrier that protects tile
// k's smem, so LDG latency overlaps the barrier wait + peer-warp compute.
// ---------------------------------------------------------------------------
__global__ void __launch_bounds__(256) gemm_kernel(const float* __restrict__ A,
                                                   const float* __restrict__ B,
                                                   const float* __restrict__ bias) {
    __shared__ float As[GEMM_BK][GEMM_BM + 4];  // transposed A tile (pad=4 keeps 16B align)
    __shared__ float Bs[GEMM_BK][GEMM_BN];

    int tid = threadIdx.x;
    int tx = tid & 15;        // 0..15 -> cols
    int ty = tid >> 4;        // 0..15 -> rows
    int bx = blockIdx.x;      // 0..4 (N blocks)
    int by = blockIdx.y;      // 0..127 (M blocks)

    const float* Ab = A + (size_t)by * GEMM_BM * KK;
    const float* Bb = B + bx * GEMM_BN;

    float acc[8][8];
#pragma unroll
    for (int i = 0; i < 8; i++)
#pragma unroll
        for (int j = 0; j < 8; j++) acc[i][j] = 0.f;

    // Loader index mapping (float4 granularity):
    // A tile: 128 rows x 16 k = 512 float4; thread handles idx=tid and tid+256
    int arow0 = tid >> 2;        // 0..63
    int ac4   = tid & 3;         // k-offset group
    // B tile: 16 rows x 128 n = 512 float4
    int brow0 = tid >> 5;        // 0..7
    int bc4   = tid & 31;

    for (int kt = 0; kt < KK; kt += GEMM_BK) {
        float4 av0 = *(const float4*)&Ab[(size_t)arow0 * KK + kt + ac4 * 4];
        float4 av1 = *(const float4*)&Ab[(size_t)(arow0 + 64) * KK + kt + ac4 * 4];
        float4 bv0 = *(const float4*)&Bb[(size_t)(kt + brow0) * NN + bc4 * 4];
        float4 bv1 = *(const float4*)&Bb[(size_t)(kt + brow0 + 8) * NN + bc4 * 4];

        __syncthreads();  // previous tile's compute done before overwrite
        As[ac4 * 4 + 0][arow0] = av0.x;
        As[ac4 * 4 + 1][arow0] = av0.y;
        As[ac4 * 4 + 2][arow0] = av0.z;
        As[ac4 * 4 + 3][arow0] = av0.w;
        As[ac4 * 4 + 0][arow0 + 64] = av1.x;
        As[ac4 * 4 + 1][arow0 + 64] = av1.y;
        As[ac4 * 4 + 2][arow0 + 64] = av1.z;
        As[ac4 * 4 + 3][arow0 + 64] = av1.w;
        *(float4*)&Bs[brow0][bc4 * 4]     = bv0;
        *(float4*)&Bs[brow0 + 8][bc4 * 4] = bv1;
        __syncthreads();

#pragma unroll
        for (int k = 0; k < GEMM_BK; k++) {
            float ar[8], br[8];
            *(float4*)&ar[0] = *(const float4*)&As[k][ty * 8];
            *(float4*)&ar[4] = *(const float4*)&As[k][ty * 8 + 4];
            *(float4*)&br[0] = *(const float4*)&Bs[k][tx * 8];
            *(float4*)&br[4] = *(const float4*)&Bs[k][tx * 8 + 4];
#pragma unroll
            for (int i = 0; i < 8; i++)
#pragma unroll
                for (int j = 0; j < 8; j++)
                    acc[i][j] = fmaf(ar[i], br[j], acc[i][j]);
        }
    }

    // Epilogue: add bias, write logits
    int colbase = bx * GEMM_BN + tx * 8;
    float bv[8];
#pragma unroll
    for (int j = 0; j < 8; j++) bv[j] = bias[colbase + j];

#pragma unroll
    for (int i = 0; i < 8; i++) {
        size_t row = (size_t)by * GEMM_BM + ty * 8 + i;
        float4 r0, r1;
        r0.x = acc[i][0] + bv[0]; r0.y = acc[i][1] + bv[1];
        r0.z = acc[i][2] + bv[2]; r0.w = acc[i][3] + bv[3];
        r1.x = acc[i][4] + bv[4]; r1.y = acc[i][5] + bv[5];
        r1.z = acc[i][6] + bv[6]; r1.w = acc[i][7] + bv[7];
        *(float4*)&g_logits[row * NN + colbase]     = r0;
        *(float4*)&g_logits[row * NN + colbase + 4] = r1;
    }
}

// ---------------------------------------------------------------------------
// Row kernel: warp per (n, g). argmax(logits+gumbel) -> codevector gather;
// softmax(logits) masked -> marginal accumulation (smem then global atomics).
// ---------------------------------------------------------------------------
__global__ void __launch_bounds__(1024) row_kernel(const float* __restrict__ gumbels,
                                                   const float* __restrict__ cb,
                                                   float* __restrict__ out) {
    __shared__ float smarg[NN];
    int tid = threadIdx.x;
    if (tid < NN) smarg[tid] = 0.f;
    __syncthreads();

    int warpid = tid >> 5;
    int lane = tid & 31;
    int w = blockIdx.x * 32 + warpid;   // flat row index n*G + g, < 32768
    int n = w >> 1;
    int g = w & 1;

    const float* lrow = g_logits + (size_t)n * NN + g * VV;
    const float* grow = gumbels + (size_t)w * VV;

    float l[10];
#pragma unroll
    for (int i = 0; i < 10; i++) l[i] = lrow[lane + 32 * i];

    // argmax of logits + gumbels (first occurrence on ties)
    float best = -3.4e38f;
    int bidx = 0;
#pragma unroll
    for (int i = 0; i < 10; i++) {
        int v = lane + 32 * i;
        float s = l[i] + grow[v];
        if (s > best) { best = s; bidx = v; }
    }
    for (int o = 16; o; o >>= 1) {
        float ob = __shfl_down_sync(0xffffffffu, best, o);
        int oi   = __shfl_down_sync(0xffffffffu, bidx, o);
        if (ob > best || (ob == best && oi < bidx)) { best = ob; bidx = oi; }
    }
    bidx = __shfl_sync(0xffffffffu, bidx, 0);

    // softmax(logits) for marginal (no gumbel, no tau)
    float mx = l[0];
#pragma unroll
    for (int i = 1; i < 10; i++) mx = fmaxf(mx, l[i]);
    for (int o = 16; o; o >>= 1) mx = fmaxf(mx, __shfl_xor_sync(0xffffffffu, mx, o));
    float e[10];
    float sum = 0.f;
#pragma unroll
    for (int i = 0; i < 10; i++) { e[i] = __expf(l[i] - mx); sum += e[i]; }
    for (int o = 16; o; o >>= 1) sum += __shfl_xor_sync(0xffffffffu, sum, o);

    float mval = g_maskf[n];
    if (mval != 0.f) {
        float inv = 1.f / sum;
#pragma unroll
        for (int i = 0; i < 10; i++)
            atomicAdd(&smarg[g * VV + lane + 32 * i], e[i] * inv);
    }

    // codevector gather: 128 floats = 32 lanes x float4
    const float4* c4 = (const float4*)(cb + (size_t)(g * VV + bidx) * DG);
    float4* o4 = (float4*)(out + (size_t)n * 256 + g * DG);
    o4[lane] = c4[lane];

    __syncthreads();
    if (tid < NN) atomicAdd(&g_marginal[tid], smarg[tid]);
}

// ---------------------------------------------------------------------------
// Final: perplexity = sum_g exp(-sum_v p*log(p+eps)), p = marginal/msum
// ---------------------------------------------------------------------------
__global__ void __launch_bounds__(640) final_kernel(float* __restrict__ out, int out_size) {
    int tid = threadIdx.x;  // 640 threads, one per (g,v)
    float msum = g_msum;
    float val = g_marginal[tid] / msum;
    float t = val * logf(val + 1e-7f);

    __shared__ float s[2];
    if (tid < 2) s[tid] = 0.f;
    __syncthreads();

    for (int o = 16; o; o >>= 1) t += __shfl_xor_sync(0xffffffffu, t, o);
    int warpid = tid >> 5;  // warps 0-9: group 0, warps 10-19: group 1
    if ((tid & 31) == 0) atomicAdd(&s[warpid >= 10 ? 1 : 0], t);
    __syncthreads();

    if (tid == 0) out[out_size - 1] = expf(-s[0]) + expf(-s[1]);
}

// ---------------------------------------------------------------------------
extern "C" void kernel_launch(void* const* d_in, const int* in_sizes, int n_in,
                              void* d_out, int out_size) {
    const float* hidden = (const float*)d_in[0];   // [8,2048,512]
    const void*  mask   = d_in[1];                 // [8,2048] bool/int32 (auto-detect)
    const float* W      = (const float*)d_in[2];   // [512,640]
    const float* b      = (const float*)d_in[3];   // [640]
    const float* cb     = (const float*)d_in[4];   // [1,640,128]
    const float* gum    = (const float*)d_in[5];   // [32768,320]
    float* out = (float*)d_out;                    // [8,2048,256] + perplexity scalar

    init_kernel<<<1, 1024>>>(mask);

    dim3 ggrid(NN / GEMM_BN, MM / GEMM_BM);        // (5, 128)
    gemm_kernel<<<ggrid, 256>>>(hidden, W, b);

    row_kernel<<<1024, 1024>>>(gum, cb, out);      // 1024 blocks x 32 warps = 32768 rows

    final_kernel<<<1, 640>>>(out, out_size);
}

// round 4
// speedup vs baseline: 1.5623x; 1.5623x over previous
#include <cuda_runtime.h>
#include <cuda_bf16.h>
#include <cstdint>

// Problem constants: B=8, S=2048, H=512, G=2, V=320, D=256
#define MM 16384      // B*S
#define KK 512        // H
#define NN 640        // G*V
#define VV 320
#define DG 128        // D/G

// ---------------------------------------------------------------------------
// Scratch (static device globals: allocation-free)
// ---------------------------------------------------------------------------
__device__ float g_logits[(size_t)MM * NN];                 // 40 MB
__device__ __nv_bfloat16 g_Ah[(size_t)MM * KK];             // 16 MB
__device__ __nv_bfloat16 g_Al[(size_t)MM * KK];             // 16 MB
__device__ __nv_bfloat16 g_Wh[(size_t)NN * KK];             // transposed [N,K]
__device__ __nv_bfloat16 g_Wl[(size_t)NN * KK];
__device__ float g_marginal[NN];
__device__ float g_maskf[MM];
__device__ float g_msum;

__device__ __forceinline__ uint32_t smem_u32(const void* p) {
    uint32_t a;
    asm("{ .reg .u64 t; cvta.to.shared.u64 t, %1; cvt.u32.u64 %0, t; }" : "=r"(a) : "l"(p));
    return a;
}
__device__ __forceinline__ void cp_async16(uint32_t saddr, const void* gaddr) {
    asm volatile("cp.async.cg.shared.global [%0], [%1], 16;" :: "r"(saddr), "l"(gaddr));
}
__device__ __forceinline__ void ldmatrix_x4(uint32_t* r, uint32_t addr) {
    asm volatile("ldmatrix.sync.aligned.m8n8.x4.shared.b16 {%0,%1,%2,%3}, [%4];"
                 : "=r"(r[0]), "=r"(r[1]), "=r"(r[2]), "=r"(r[3]) : "r"(addr));
}
__device__ __forceinline__ void mma16816(float* c, const uint32_t* a, uint32_t b0, uint32_t b1) {
    asm volatile("mma.sync.aligned.m16n8k16.row.col.f32.bf16.bf16.f32 "
                 "{%0,%1,%2,%3}, {%4,%5,%6,%7}, {%8,%9}, {%0,%1,%2,%3};"
                 : "+f"(c[0]), "+f"(c[1]), "+f"(c[2]), "+f"(c[3])
                 : "r"(a[0]), "r"(a[1]), "r"(a[2]), "r"(a[3]), "r"(b0), "r"(b1));
}

// ---------------------------------------------------------------------------
// Init: zero marginal, detect mask dtype (int32 vs uint8), expand mask, sum it
// ---------------------------------------------------------------------------
__global__ void __launch_bounds__(1024) init_kernel(const void* __restrict__ maskraw) {
    int tid = threadIdx.x;
    if (tid < NN) g_marginal[tid] = 0.f;

    __shared__ int isU8;
    if (tid == 0) isU8 = 0;
    __syncthreads();

    const unsigned char* mb = (const unsigned char*)maskraw;
    int any = 0;
    for (int i = tid; i < MM; i += 1024)
        if ((i & 3) && mb[i]) any = 1;
    if (any) isU8 = 1;
    __syncthreads();

    bool u8 = (isU8 != 0);
    const int* mi = (const int*)maskraw;
    float local = 0.f;
    for (int i = tid; i < MM; i += 1024) {
        bool on = u8 ? (mb[i] != 0) : (mi[i] != 0);
        float v = on ? 1.f : 0.f;
        g_maskf[i] = v;
        local += v;
    }
    __shared__ float red[32];
    for (int o = 16; o; o >>= 1) local += __shfl_xor_sync(0xffffffffu, local, o);
    if ((tid & 31) == 0) red[tid >> 5] = local;
    __syncthreads();
    if (tid < 32) {
        float s = red[tid];
        for (int o = 16; o; o >>= 1) s += __shfl_xor_sync(0xffffffffu, s, o);
        if (tid == 0) g_msum = s;
    }
}

// ---------------------------------------------------------------------------
// Convert hidden fp32 -> split bf16 (hi + lo)
// ---------------------------------------------------------------------------
__global__ void __launch_bounds__(256) convert_A_kernel(const float* __restrict__ A) {
    size_t i4 = (size_t)blockIdx.x * 256 + threadIdx.x;  // float4 index
    if (i4 >= (size_t)MM * KK / 4) return;
    float4 v = ((const float4*)A)[i4];
    __nv_bfloat16 h0 = __float2bfloat16(v.x), h1 = __float2bfloat16(v.y);
    __nv_bfloat16 h2 = __float2bfloat16(v.z), h3 = __float2bfloat16(v.w);
    __nv_bfloat16 l0 = __float2bfloat16(v.x - __bfloat162float(h0));
    __nv_bfloat16 l1 = __float2bfloat16(v.y - __bfloat162float(h1));
    __nv_bfloat16 l2 = __float2bfloat16(v.z - __bfloat162float(h2));
    __nv_bfloat16 l3 = __float2bfloat16(v.w - __bfloat162float(h3));
    __nv_bfloat162 hv0, hv1, lv0, lv1;
    hv0.x = h0; hv0.y = h1; hv1.x = h2; hv1.y = h3;
    lv0.x = l0; lv0.y = l1; lv1.x = l2; lv1.y = l3;
    ((uint2*)g_Ah)[i4] = make_uint2(*(uint32_t*)&hv0, *(uint32_t*)&hv1);
    ((uint2*)g_Al)[i4] = make_uint2(*(uint32_t*)&lv0, *(uint32_t*)&lv1);
}

// ---------------------------------------------------------------------------
// Convert + transpose W fp32 [K,N] -> split bf16 [N,K]
// ---------------------------------------------------------------------------
__global__ void __launch_bounds__(256) convert_W_kernel(const float* __restrict__ W) {
    int idx = blockIdx.x * 256 + threadIdx.x;  // over N*K
    if (idx >= NN * KK) return;
    int n = idx / KK, k = idx % KK;
    float a = W[(size_t)k * NN + n];
    __nv_bfloat16 h = __float2bfloat16(a);
    __nv_bfloat16 l = __float2bfloat16(a - __bfloat162float(h));
    g_Wh[idx] = h;
    g_Wl[idx] = l;
}

// ---------------------------------------------------------------------------
// mma.sync split-bf16 GEMM: logits[M,N] = A[M,K] @ W[K,N] + bias
// CTA 128x128, 8 warps (64x32 each), BK=32, double-buffered cp.async.
// Effective K = 3*512 (phases: Ah*Wh, Ah*Wl, Al*Wh), fp32 register accum.
// ---------------------------------------------------------------------------
#define BM 128
#define BN 128
#define BKC 32
#define SSTR 40                       // padded smem row stride (elements)
#define NCHUNK 48                     // 3 phases * 16 chunks

__global__ void __launch_bounds__(256, 2) mma_gemm_kernel(const float* __restrict__ bias) {
    __shared__ __nv_bfloat16 As[2][BM][SSTR];
    __shared__ __nv_bfloat16 Bs[2][BN][SSTR];

    int tid = threadIdx.x;
    int lane = tid & 31;
    int wid = tid >> 5;
    int wr = wid >> 2;                // 0..1  (warp row: 64 m each)
    int wc = wid & 3;                 // 0..3  (warp col: 32 n each)
    int m0 = blockIdx.y * BM;
    int n0 = blockIdx.x * BN;

    float acc[4][4][4];
#pragma unroll
    for (int i = 0; i < 4; i++)
#pragma unroll
        for (int j = 0; j < 4; j++)
#pragma unroll
            for (int r = 0; r < 4; r++) acc[i][j][r] = 0.f;

    uint32_t sA0 = smem_u32(&As[0][0][0]);
    uint32_t sB0 = smem_u32(&Bs[0][0][0]);
    const uint32_t STAGE = BM * SSTR * 2;   // bytes per stage (10240)

    // Per-thread load slots: idx, idx+256 over 512 16B segments per matrix
    int row0 = tid >> 2, seg0 = tid & 3;
    int row1 = (tid + 256) >> 2, seg1 = (tid + 256) & 3;

#define LOAD_CHUNK(kc, buf) do {                                              \
        int phase = (kc) >> 4;                                                \
        int koff = ((kc) & 15) * BKC;                                         \
        const __nv_bfloat16* Asrc = (phase < 2) ? g_Ah : g_Al;                \
        const __nv_bfloat16* Bsrc = (phase == 1) ? g_Wl : g_Wh;               \
        cp_async16(sA0 + (buf) * STAGE + row0 * (SSTR * 2) + seg0 * 16,       \
                   Asrc + (size_t)(m0 + row0) * KK + koff + seg0 * 8);        \
        cp_async16(sA0 + (buf) * STAGE + row1 * (SSTR * 2) + seg1 * 16,       \
                   Asrc + (size_t)(m0 + row1) * KK + koff + seg1 * 8);        \
        cp_async16(sB0 + (buf) * STAGE + row0 * (SSTR * 2) + seg0 * 16,       \
                   Bsrc + (size_t)(n0 + row0) * KK + koff + seg0 * 8);        \
        cp_async16(sB0 + (buf) * STAGE + row1 * (SSTR * 2) + seg1 * 16,       \
                   Bsrc + (size_t)(n0 + row1) * KK + koff + seg1 * 8);        \
        asm volatile("cp.async.commit_group;");                               \
    } while (0)

    LOAD_CHUNK(0, 0);

    // ldmatrix per-lane addresses (byte offsets within a stage)
    uint32_t aoff = (uint32_t)((wr * 64 + (lane & 15)) * (SSTR * 2) + ((lane >> 4) * 8) * 2);
    uint32_t boff = (uint32_t)((wc * 32 + (lane & 7) + ((lane >> 4) & 1) * 8) * (SSTR * 2)
                               + (((lane >> 3) & 1) * 8) * 2);

    for (int kc = 0; kc < NCHUNK; kc++) {
        int buf = kc & 1;
        if (kc + 1 < NCHUNK) {
            LOAD_CHUNK(kc + 1, buf ^ 1);
            asm volatile("cp.async.wait_group 1;");
        } else {
            asm volatile("cp.async.wait_group 0;");
        }
        __syncthreads();

        uint32_t aBase = sA0 + buf * STAGE + aoff;
        uint32_t bBase = sB0 + buf * STAGE + boff;
#pragma unroll
        for (int kk = 0; kk < 2; kk++) {
            uint32_t kb = kk * 32;  // 16 bf16 = 32 bytes
            uint32_t afr[4][4], bfr[2][4];
#pragma unroll
            for (int mi = 0; mi < 4; mi++)
                ldmatrix_x4(afr[mi], aBase + mi * 16 * (SSTR * 2) + kb);
#pragma unroll
            for (int nj = 0; nj < 2; nj++)
                ldmatrix_x4(bfr[nj], bBase + nj * 16 * (SSTR * 2) + kb);
#pragma unroll
            for (int mi = 0; mi < 4; mi++)
#pragma unroll
                for (int ni = 0; ni < 4; ni++) {
                    uint32_t b0 = bfr[ni >> 1][(ni & 1) * 2];
                    uint32_t b1 = bfr[ni >> 1][(ni & 1) * 2 + 1];
                    mma16816(acc[mi][ni], afr[mi], b0, b1);
                }
        }
        __syncthreads();
    }

    // Epilogue: bias add + store
    int l4 = lane >> 2, l2 = (lane & 3) * 2;
    float2 bb[4];
#pragma unroll
    for (int ni = 0; ni < 4; ni++) {
        int col = n0 + wc * 32 + ni * 8 + l2;
        bb[ni].x = __ldg(&bias[col]);
        bb[ni].y = __ldg(&bias[col + 1]);
    }
#pragma unroll
    for (int mi = 0; mi < 4; mi++) {
        int row = m0 + wr * 64 + mi * 16 + l4;
#pragma unroll
        for (int ni = 0; ni < 4; ni++) {
            int col = n0 + wc * 32 + ni * 8 + l2;
            float2 v0 = make_float2(acc[mi][ni][0] + bb[ni].x, acc[mi][ni][1] + bb[ni].y);
            float2 v1 = make_float2(acc[mi][ni][2] + bb[ni].x, acc[mi][ni][3] + bb[ni].y);
            *(float2*)&g_logits[(size_t)row * NN + col] = v0;
            *(float2*)&g_logits[(size_t)(row + 8) * NN + col] = v1;
        }
    }
}

// ---------------------------------------------------------------------------
// Exact fp32 rescore of one candidate column (warp-cooperative)
// ---------------------------------------------------------------------------
__device__ __forceinline__ float exact_score(const float* __restrict__ hidden,
                                             const float* __restrict__ W,
                                             const float* __restrict__ bias,
                                             const float* __restrict__ grow,
                                             int n, int col, int v, int lane) {
    const float* hrow = hidden + (size_t)n * KK;
    float s = 0.f;
#pragma unroll 4
    for (int j = lane; j < KK; j += 32)
        s = fmaf(hrow[j], W[(size_t)j * NN + col], s);
    for (int o = 16; o; o >>= 1) s += __shfl_xor_sync(0xffffffffu, s, o);
    return s + bias[col] + grow[v];
}

// ---------------------------------------------------------------------------
// Row kernel: warp per (n, g). argmax(logits+gumbel) with exact-rescore of
// near-tie rows -> codevector gather; softmax(logits) masked -> marginal.
// ---------------------------------------------------------------------------
__global__ void __launch_bounds__(1024) row_kernel(const float* __restrict__ gumbels,
                                                   const float* __restrict__ cb,
                                                   float* __restrict__ out,
                                                   const float* __restrict__ hidden,
                                                   const float* __restrict__ W,
                                                   const float* __restrict__ bias) {
    __shared__ float smarg[NN];
    int tid = threadIdx.x;
    if (tid < NN) smarg[tid] = 0.f;
    __syncthreads();

    int warpid = tid >> 5;
    int lane = tid & 31;
    int w = blockIdx.x * 32 + warpid;   // flat row index n*G + g
    int n = w >> 1;
    int g = w & 1;

    const float* lrow = g_logits + (size_t)n * NN + g * VV;
    const float* grow = gumbels + (size_t)w * VV;

    float l[10], sc[10];
#pragma unroll
    for (int i = 0; i < 10; i++) {
        l[i] = lrow[lane + 32 * i];
        sc[i] = l[i] + grow[lane + 32 * i];
    }

    // argmax of logits + gumbels (first occurrence on ties)
    float best = -3.4e38f;
    int bidx = 0;
#pragma unroll
    for (int i = 0; i < 10; i++) {
        int v = lane + 32 * i;
        if (sc[i] > best) { best = sc[i]; bidx = v; }
    }
    for (int o = 16; o; o >>= 1) {
        float ob = __shfl_down_sync(0xffffffffu, best, o);
        int oi   = __shfl_down_sync(0xffffffffu, bidx, o);
        if (ob > best || (ob == best && oi < bidx)) { best = ob; bidx = oi; }
    }
    best = __shfl_sync(0xffffffffu, best, 0);
    bidx = __shfl_sync(0xffffffffu, bidx, 0);

    // second best (excluding bidx), for the near-tie test
    float sec = -3.4e38f;
#pragma unroll
    for (int i = 0; i < 10; i++) {
        int v = lane + 32 * i;
        if (v != bidx && sc[i] > sec) sec = sc[i];
    }
    for (int o = 16; o; o >>= 1) sec = fmaxf(sec, __shfl_xor_sync(0xffffffffu, sec, o));

    // near-tie: rescore all candidates within 1e-3 of best exactly in fp32
    if (best - sec < 1e-3f) {
        float thr = best - 1e-3f;
        float exbest = -3.4e38f;
        int exidx = VV;
        int col0 = g * VV;
#pragma unroll
        for (int i = 0; i < 10; i++) {
            unsigned mset = __ballot_sync(0xffffffffu, sc[i] >= thr);
            while (mset) {
                int src = __ffs(mset) - 1;
                mset &= mset - 1;
                int v = src + 32 * i;
                float ex = exact_score(hidden, W, bias, grow, n, col0 + v, v, lane);
                if (ex > exbest || (ex == exbest && v < exidx)) { exbest = ex; exidx = v; }
            }
        }
        bidx = exidx;
    }

    // softmax(logits) for marginal (no gumbel, no tau)
    float mx = l[0];
#pragma unroll
    for (int i = 1; i < 10; i++) mx = fmaxf(mx, l[i]);
    for (int o = 16; o; o >>= 1) mx = fmaxf(mx, __shfl_xor_sync(0xffffffffu, mx, o));
    float e[10];
    float sum = 0.f;
#pragma unroll
    for (int i = 0; i < 10; i++) { e[i] = __expf(l[i] - mx); sum += e[i]; }
    for (int o = 16; o; o >>= 1) sum += __shfl_xor_sync(0xffffffffu, sum, o);

    if (g_maskf[n] != 0.f) {
        float inv = 1.f / sum;
#pragma unroll
        for (int i = 0; i < 10; i++)
            atomicAdd(&smarg[g * VV + lane + 32 * i], e[i] * inv);
    }

    // codevector gather: 128 floats = 32 lanes x float4
    const float4* c4 = (const float4*)(cb + (size_t)(g * VV + bidx) * DG);
    float4* o4 = (float4*)(out + (size_t)n * 256 + g * DG);
    o4[lane] = c4[lane];

    __syncthreads();
    if (tid < NN) atomicAdd(&g_marginal[tid], smarg[tid]);
}

// ---------------------------------------------------------------------------
// Final: perplexity = sum_g exp(-sum_v p*log(p+eps)), p = marginal/msum
// ---------------------------------------------------------------------------
__global__ void __launch_bounds__(640) final_kernel(float* __restrict__ out, int out_size) {
    int tid = threadIdx.x;
    float msum = g_msum;
    float val = g_marginal[tid] / msum;
    float t = val * logf(val + 1e-7f);

    __shared__ float s[2];
    if (tid < 2) s[tid] = 0.f;
    __syncthreads();

    for (int o = 16; o; o >>= 1) t += __shfl_xor_sync(0xffffffffu, t, o);
    int warpid = tid >> 5;
    if ((tid & 31) == 0) atomicAdd(&s[warpid >= 10 ? 1 : 0], t);
    __syncthreads();

    if (tid == 0) out[out_size - 1] = expf(-s[0]) + expf(-s[1]);
}

// ---------------------------------------------------------------------------
extern "C" void kernel_launch(void* const* d_in, const int* in_sizes, int n_in,
                              void* d_out, int out_size) {
    const float* hidden = (const float*)d_in[0];   // [8,2048,512]
    const void*  mask   = d_in[1];                 // [8,2048]
    const float* W      = (const float*)d_in[2];   // [512,640]
    const float* b      = (const float*)d_in[3];   // [640]
    const float* cb     = (const float*)d_in[4];   // [1,640,128]
    const float* gum    = (const float*)d_in[5];   // [32768,320]
    float* out = (float*)d_out;

    init_kernel<<<1, 1024>>>(mask);
    convert_A_kernel<<<(MM * KK / 4 + 255) / 256, 256>>>(hidden);
    convert_W_kernel<<<(NN * KK + 255) / 256, 256>>>(W);

    dim3 ggrid(NN / BN, MM / BM);   // (5, 128)
    mma_gemm_kernel<<<ggrid, 256>>>(b);

    row_kernel<<<1024, 1024>>>(gum, cb, out, hidden, W, b);

    final_kernel<<<1, 640>>>(out, out_size);
}

// round 5
// speedup vs baseline: 2.6396x; 1.6895x over previous
#include <cuda_runtime.h>
#include <cuda_bf16.h>
#include <cstdint>

// Problem constants: B=8, S=2048, H=512, G=2, V=320, D=256
#define MM 16384      // B*S
#define KK 512        // H
#define NN 640        // G*V
#define VV 320
#define DG 128        // D/G

// ---------------------------------------------------------------------------
// Scratch (static device globals: allocation-free)
// ---------------------------------------------------------------------------
__device__ float g_logits[(size_t)MM * NN];                 // 40 MB
__device__ __nv_bfloat16 g_Ah[(size_t)MM * KK];             // 16 MB
__device__ __nv_bfloat16 g_Wh[(size_t)NN * KK];             // transposed [N,K]
__device__ float g_marginal[NN];
__device__ float g_maskf[MM];
__device__ float g_msum;

__device__ __forceinline__ uint32_t smem_u32(const void* p) {
    uint32_t a;
    asm("{ .reg .u64 t; cvta.to.shared.u64 t, %1; cvt.u32.u64 %0, t; }" : "=r"(a) : "l"(p));
    return a;
}
__device__ __forceinline__ void cp_async16(uint32_t saddr, const void* gaddr) {
    asm volatile("cp.async.cg.shared.global [%0], [%1], 16;" :: "r"(saddr), "l"(gaddr));
}
__device__ __forceinline__ void ldmatrix_x4(uint32_t* r, uint32_t addr) {
    asm volatile("ldmatrix.sync.aligned.m8n8.x4.shared.b16 {%0,%1,%2,%3}, [%4];"
                 : "=r"(r[0]), "=r"(r[1]), "=r"(r[2]), "=r"(r[3]) : "r"(addr));
}
__device__ __forceinline__ void mma16816(float* c, const uint32_t* a, uint32_t b0, uint32_t b1) {
    asm volatile("mma.sync.aligned.m16n8k16.row.col.f32.bf16.bf16.f32 "
                 "{%0,%1,%2,%3}, {%4,%5,%6,%7}, {%8,%9}, {%0,%1,%2,%3};"
                 : "+f"(c[0]), "+f"(c[1]), "+f"(c[2]), "+f"(c[3])
                 : "r"(a[0]), "r"(a[1]), "r"(a[2]), "r"(a[3]), "r"(b0), "r"(b1));
}

// ---------------------------------------------------------------------------
// Init: zero marginal, detect mask dtype (int32 vs uint8), expand mask, sum it
// ---------------------------------------------------------------------------
__global__ void __launch_bounds__(1024) init_kernel(const void* __restrict__ maskraw) {
    int tid = threadIdx.x;
    if (tid < NN) g_marginal[tid] = 0.f;

    __shared__ int isU8;
    if (tid == 0) isU8 = 0;
    __syncthreads();

    const unsigned char* mb = (const unsigned char*)maskraw;
    int any = 0;
    for (int i = tid; i < MM; i += 1024)
        if ((i & 3) && mb[i]) any = 1;
    if (any) isU8 = 1;
    __syncthreads();

    bool u8 = (isU8 != 0);
    const int* mi = (const int*)maskraw;
    float local = 0.f;
    for (int i = tid; i < MM; i += 1024) {
        bool on = u8 ? (mb[i] != 0) : (mi[i] != 0);
        float v = on ? 1.f : 0.f;
        g_maskf[i] = v;
        local += v;
    }
    __shared__ float red[32];
    for (int o = 16; o; o >>= 1) local += __shfl_xor_sync(0xffffffffu, local, o);
    if ((tid & 31) == 0) red[tid >> 5] = local;
    __syncthreads();
    if (tid < 32) {
        float s = red[tid];
        for (int o = 16; o; o >>= 1) s += __shfl_xor_sync(0xffffffffu, s, o);
        if (tid == 0) g_msum = s;
    }
}

// ---------------------------------------------------------------------------
// Convert hidden fp32 -> bf16
// ---------------------------------------------------------------------------
__global__ void __launch_bounds__(256) convert_A_kernel(const float* __restrict__ A) {
    size_t i4 = (size_t)blockIdx.x * 256 + threadIdx.x;  // float4 index
    if (i4 >= (size_t)MM * KK / 4) return;
    float4 v = ((const float4*)A)[i4];
    __nv_bfloat162 h0, h1;
    h0.x = __float2bfloat16(v.x); h0.y = __float2bfloat16(v.y);
    h1.x = __float2bfloat16(v.z); h1.y = __float2bfloat16(v.w);
    ((uint2*)g_Ah)[i4] = make_uint2(*(uint32_t*)&h0, *(uint32_t*)&h1);
}

// ---------------------------------------------------------------------------
// Convert + transpose W fp32 [K,N] -> bf16 [N,K]
// ---------------------------------------------------------------------------
__global__ void __launch_bounds__(256) convert_W_kernel(const float* __restrict__ W) {
    int idx = blockIdx.x * 256 + threadIdx.x;  // over N*K
    if (idx >= NN * KK) return;
    int n = idx / KK, k = idx % KK;
    g_Wh[idx] = __float2bfloat16(W[(size_t)k * NN + n]);
}

// ---------------------------------------------------------------------------
// mma.sync bf16 GEMM: logits[M,N] = A[M,K] @ W[K,N] + bias
// CTA 128x128, 8 warps (64x32 each), BK=32, 4-stage cp.async ring,
// one __syncthreads per chunk, fp32 register accumulators.
// ---------------------------------------------------------------------------
#define BM 128
#define BN 128
#define BKC 32
#define SSTR 40                       // padded smem row stride (elements)
#define NCHUNK 16                     // K / BKC
#define STAGES 4
#define AB_OFF (BM * SSTR * 2)        // 10240: B offset within a stage
#define STAGE_BYTES (2 * BM * SSTR * 2)   // 20480 per stage (A + B)
#define GEMM_SMEM (STAGES * STAGE_BYTES)  // 81920

__global__ void __launch_bounds__(256, 2) mma_gemm_kernel(const float* __restrict__ bias) {
    extern __shared__ char smem[];
    uint32_t sbase = smem_u32(smem);

    int tid = threadIdx.x;
    int lane = tid & 31;
    int wid = tid >> 5;
    int wr = wid >> 2;                // 0..1  (warp row: 64 m each)
    int wc = wid & 3;                 // 0..3  (warp col: 32 n each)
    int m0 = blockIdx.y * BM;
    int n0 = blockIdx.x * BN;

    float acc[4][4][4];
#pragma unroll
    for (int i = 0; i < 4; i++)
#pragma unroll
        for (int j = 0; j < 4; j++)
#pragma unroll
            for (int r = 0; r < 4; r++) acc[i][j][r] = 0.f;

    // Per-thread load slots: rows tid/4 and tid/4+64, 16B segment tid%4
    int row0 = tid >> 2, seg0 = tid & 3;
    int row1 = row0 + 64;

#define LOAD_CHUNK(kc, st) do {                                               \
        int koff = (kc) * BKC;                                                \
        uint32_t sb = sbase + (st) * STAGE_BYTES;                             \
        cp_async16(sb + row0 * (SSTR * 2) + seg0 * 16,                        \
                   g_Ah + (size_t)(m0 + row0) * KK + koff + seg0 * 8);        \
        cp_async16(sb + row1 * (SSTR * 2) + seg0 * 16,                        \
                   g_Ah + (size_t)(m0 + row1) * KK + koff + seg0 * 8);        \
        cp_async16(sb + AB_OFF + row0 * (SSTR * 2) + seg0 * 16,               \
                   g_Wh + (size_t)(n0 + row0) * KK + koff + seg0 * 8);        \
        cp_async16(sb + AB_OFF + row1 * (SSTR * 2) + seg0 * 16,               \
                   g_Wh + (size_t)(n0 + row1) * KK + koff + seg0 * 8);        \
    } while (0)

    // Prologue: stages 0..2 in flight (3 commit groups)
    LOAD_CHUNK(0, 0); asm volatile("cp.async.commit_group;");
    LOAD_CHUNK(1, 1); asm volatile("cp.async.commit_group;");
    LOAD_CHUNK(2, 2); asm volatile("cp.async.commit_group;");

    // ldmatrix per-lane addresses (byte offsets within a stage)
    uint32_t aoff = (uint32_t)((wr * 64 + (lane & 15)) * (SSTR * 2) + ((lane >> 4) * 8) * 2);
    uint32_t boff = (uint32_t)(AB_OFF + (wc * 32 + (lane & 7) + ((lane >> 4) & 1) * 8) * (SSTR * 2)
                               + (((lane >> 3) & 1) * 8) * 2);

    for (int kc = 0; kc < NCHUNK; kc++) {
        // chunk kc lives in group #kc; newest committed group = kc+2
        asm volatile("cp.async.wait_group 2;");
        __syncthreads();

        // prefetch chunk kc+3 into stage (kc+3)&3 == (kc-1)&3 (safe: its
        // compute finished before this barrier). Always commit (possibly
        // empty) to keep group numbering uniform for wait_group 2.
        if (kc + 3 < NCHUNK) LOAD_CHUNK(kc + 3, (kc + 3) & 3);
        asm volatile("cp.async.commit_group;");

        uint32_t stb = sbase + (kc & 3) * STAGE_BYTES;
        uint32_t aBase = stb + aoff;
        uint32_t bBase = stb + boff;
#pragma unroll
        for (int kk = 0; kk < 2; kk++) {
            uint32_t kb = kk * 32;  // 16 bf16 = 32 bytes
            uint32_t afr[4][4], bfr[2][4];
#pragma unroll
            for (int mi = 0; mi < 4; mi++)
                ldmatrix_x4(afr[mi], aBase + mi * 16 * (SSTR * 2) + kb);
#pragma unroll
            for (int nj = 0; nj < 2; nj++)
                ldmatrix_x4(bfr[nj], bBase + nj * 16 * (SSTR * 2) + kb);
#pragma unroll
            for (int mi = 0; mi < 4; mi++)
#pragma unroll
                for (int ni = 0; ni < 4; ni++) {
                    uint32_t b0 = bfr[ni >> 1][(ni & 1) * 2];
                    uint32_t b1 = bfr[ni >> 1][(ni & 1) * 2 + 1];
                    mma16816(acc[mi][ni], afr[mi], b0, b1);
                }
        }
    }

    // Epilogue: bias add + store
    int l4 = lane >> 2, l2 = (lane & 3) * 2;
    float2 bb[4];
#pragma unroll
    for (int ni = 0; ni < 4; ni++) {
        int col = n0 + wc * 32 + ni * 8 + l2;
        bb[ni].x = __ldg(&bias[col]);
        bb[ni].y = __ldg(&bias[col + 1]);
    }
#pragma unroll
    for (int mi = 0; mi < 4; mi++) {
        int row = m0 + wr * 64 + mi * 16 + l4;
#pragma unroll
        for (int ni = 0; ni < 4; ni++) {
            int col = n0 + wc * 32 + ni * 8 + l2;
            float2 v0 = make_float2(acc[mi][ni][0] + bb[ni].x, acc[mi][ni][1] + bb[ni].y);
            float2 v1 = make_float2(acc[mi][ni][2] + bb[ni].x, acc[mi][ni][3] + bb[ni].y);
            *(float2*)&g_logits[(size_t)row * NN + col] = v0;
            *(float2*)&g_logits[(size_t)(row + 8) * NN + col] = v1;
        }
    }
}

// ---------------------------------------------------------------------------
// Exact fp32 rescore of one candidate column (warp-cooperative)
// ---------------------------------------------------------------------------
__device__ __forceinline__ float exact_score(const float* __restrict__ hidden,
                                             const float* __restrict__ W,
                                             const float* __restrict__ bias,
                                             const float* __restrict__ grow,
                                             int n, int col, int v, int lane) {
    const float* hrow = hidden + (size_t)n * KK;
    float s = 0.f;
#pragma unroll 4
    for (int j = lane; j < KK; j += 32)
        s = fmaf(hrow[j], W[(size_t)j * NN + col], s);
    for (int o = 16; o; o >>= 1) s += __shfl_xor_sync(0xffffffffu, s, o);
    return s + bias[col] + grow[v];
}

// ---------------------------------------------------------------------------
// Row kernel: warp per (n, g). argmax(logits+gumbel); rows whose bf16-logit
// top-2 gap < 2e-2 get exact fp32 rescoring of all candidates within 2.4e-2.
// softmax(logits) masked -> marginal.
// ---------------------------------------------------------------------------
#define RESCORE_GAP  2.0e-2f
#define RESCORE_WIN  2.4e-2f

__global__ void __launch_bounds__(1024) row_kernel(const float* __restrict__ gumbels,
                                                   const float* __restrict__ cb,
                                                   float* __restrict__ out,
                                                   const float* __restrict__ hidden,
                                                   const float* __restrict__ W,
                                                   const float* __restrict__ bias) {
    __shared__ float smarg[NN];
    int tid = threadIdx.x;
    if (tid < NN) smarg[tid] = 0.f;
    __syncthreads();

    int warpid = tid >> 5;
    int lane = tid & 31;
    int w = blockIdx.x * 32 + warpid;   // flat row index n*G + g
    int n = w >> 1;
    int g = w & 1;

    const float* lrow = g_logits + (size_t)n * NN + g * VV;
    const float* grow = gumbels + (size_t)w * VV;

    float l[10], sc[10];
#pragma unroll
    for (int i = 0; i < 10; i++) {
        l[i] = lrow[lane + 32 * i];
        sc[i] = l[i] + grow[lane + 32 * i];
    }

    // argmax of logits + gumbels (first occurrence on ties)
    float best = -3.4e38f;
    int bidx = 0;
#pragma unroll
    for (int i = 0; i < 10; i++) {
        int v = lane + 32 * i;
        if (sc[i] > best) { best = sc[i]; bidx = v; }
    }
    for (int o = 16; o; o >>= 1) {
        float ob = __shfl_down_sync(0xffffffffu, best, o);
        int oi   = __shfl_down_sync(0xffffffffu, bidx, o);
        if (ob > best || (ob == best && oi < bidx)) { best = ob; bidx = oi; }
    }
    best = __shfl_sync(0xffffffffu, best, 0);
    bidx = __shfl_sync(0xffffffffu, bidx, 0);

    // second best (excluding bidx), for the near-tie test
    float sec = -3.4e38f;
#pragma unroll
    for (int i = 0; i < 10; i++) {
        int v = lane + 32 * i;
        if (v != bidx && sc[i] > sec) sec = sc[i];
    }
    for (int o = 16; o; o >>= 1) sec = fmaxf(sec, __shfl_xor_sync(0xffffffffu, sec, o));

    // near-tie: rescore all candidates within the window exactly in fp32
    if (best - sec < RESCORE_GAP) {
        float thr = best - RESCORE_WIN;
        float exbest = -3.4e38f;
        int exidx = VV;
        int col0 = g * VV;
#pragma unroll
        for (int i = 0; i < 10; i++) {
            unsigned mset = __ballot_sync(0xffffffffu, sc[i] >= thr);
            while (mset) {
                int src = __ffs(mset) - 1;
                mset &= mset - 1;
                int v = src + 32 * i;
                float ex = exact_score(hidden, W, bias, grow, n, col0 + v, v, lane);
                if (ex > exbest || (ex == exbest && v < exidx)) { exbest = ex; exidx = v; }
            }
        }
        bidx = exidx;
    }

    // softmax(logits) for marginal (no gumbel, no tau)
    float mx = l[0];
#pragma unroll
    for (int i = 1; i < 10; i++) mx = fmaxf(mx, l[i]);
    for (int o = 16; o; o >>= 1) mx = fmaxf(mx, __shfl_xor_sync(0xffffffffu, mx, o));
    float e[10];
    float sum = 0.f;
#pragma unroll
    for (int i = 0; i < 10; i++) { e[i] = __expf(l[i] - mx); sum += e[i]; }
    for (int o = 16; o; o >>= 1) sum += __shfl_xor_sync(0xffffffffu, sum, o);

    if (g_maskf[n] != 0.f) {
        float inv = 1.f / sum;
#pragma unroll
        for (int i = 0; i < 10; i++)
            atomicAdd(&smarg[g * VV + lane + 32 * i], e[i] * inv);
    }

    // codevector gather: 128 floats = 32 lanes x float4
    const float4* c4 = (const float4*)(cb + (size_t)(g * VV + bidx) * DG);
    float4* o4 = (float4*)(out + (size_t)n * 256 + g * DG);
    o4[lane] = c4[lane];

    __syncthreads();
    if (tid < NN) atomicAdd(&g_marginal[tid], smarg[tid]);
}

// ---------------------------------------------------------------------------
// Final: perplexity = sum_g exp(-sum_v p*log(p+eps)), p = marginal/msum
// ---------------------------------------------------------------------------
__global__ void __launch_bounds__(640) final_kernel(float* __restrict__ out, int out_size) {
    int tid = threadIdx.x;
    float msum = g_msum;
    float val = g_marginal[tid] / msum;
    float t = val * logf(val + 1e-7f);

    __shared__ float s[2];
    if (tid < 2) s[tid] = 0.f;
    __syncthreads();

    for (int o = 16; o; o >>= 1) t += __shfl_xor_sync(0xffffffffu, t, o);
    int warpid = tid >> 5;
    if ((tid & 31) == 0) atomicAdd(&s[warpid >= 10 ? 1 : 0], t);
    __syncthreads();

    if (tid == 0) out[out_size - 1] = expf(-s[0]) + expf(-s[1]);
}

// ---------------------------------------------------------------------------
extern "C" void kernel_launch(void* const* d_in, const int* in_sizes, int n_in,
                              void* d_out, int out_size) {
    const float* hidden = (const float*)d_in[0];   // [8,2048,512]
    const void*  mask   = d_in[1];                 // [8,2048]
    const float* W      = (const float*)d_in[2];   // [512,640]
    const float* b      = (const float*)d_in[3];   // [640]
    const float* cb     = (const float*)d_in[4];   // [1,640,128]
    const float* gum    = (const float*)d_in[5];   // [32768,320]
    float* out = (float*)d_out;

    cudaFuncSetAttribute(mma_gemm_kernel,
                         cudaFuncAttributeMaxDynamicSharedMemorySize, GEMM_SMEM);

    init_kernel<<<1, 1024>>>(mask);
    convert_A_kernel<<<(MM * KK / 4 + 255) / 256, 256>>>(hidden);
    convert_W_kernel<<<(NN * KK + 255) / 256, 256>>>(W);

    dim3 ggrid(NN / BN, MM / BM);   // (5, 128)
    mma_gemm_kernel<<<ggrid, 256, GEMM_SMEM>>>(b);

    row_kernel<<<1024, 1024>>>(gum, cb, out, hidden, W, b);

    final_kernel<<<1, 640>>>(out, out_size);
}

// round 6
// speedup vs baseline: 2.7761x; 1.0517x over previous
#include <cuda_runtime.h>
#include <cuda_bf16.h>
#include <cstdint>

// Problem constants: B=8, S=2048, H=512, G=2, V=320, D=256
#define MM 16384      // B*S
#define KK 512        // H
#define NN 640        // G*V
#define VV 320
#define DG 128        // D/G

// ---------------------------------------------------------------------------
// Scratch (static device globals: allocation-free)
// ---------------------------------------------------------------------------
__device__ float g_logits[(size_t)MM * NN];                 // 40 MB
__device__ __nv_bfloat16 g_Ah[(size_t)MM * KK];             // 16 MB
__device__ __nv_bfloat16 g_Wh[(size_t)NN * KK];             // transposed [N,K]
__device__ float g_marginal[NN];
__device__ float g_maskf[MM];
__device__ float g_msum;

__device__ __forceinline__ uint32_t smem_u32(const void* p) {
    uint32_t a;
    asm("{ .reg .u64 t; cvta.to.shared.u64 t, %1; cvt.u32.u64 %0, t; }" : "=r"(a) : "l"(p));
    return a;
}
__device__ __forceinline__ void cp_async16(uint32_t saddr, const void* gaddr) {
    asm volatile("cp.async.cg.shared.global [%0], [%1], 16;" :: "r"(saddr), "l"(gaddr));
}
__device__ __forceinline__ void ldmatrix_x4(uint32_t* r, uint32_t addr) {
    asm volatile("ldmatrix.sync.aligned.m8n8.x4.shared.b16 {%0,%1,%2,%3}, [%4];"
                 : "=r"(r[0]), "=r"(r[1]), "=r"(r[2]), "=r"(r[3]) : "r"(addr));
}
__device__ __forceinline__ void mma16816(float* c, const uint32_t* a, uint32_t b0, uint32_t b1) {
    asm volatile("mma.sync.aligned.m16n8k16.row.col.f32.bf16.bf16.f32 "
                 "{%0,%1,%2,%3}, {%4,%5,%6,%7}, {%8,%9}, {%0,%1,%2,%3};"
                 : "+f"(c[0]), "+f"(c[1]), "+f"(c[2]), "+f"(c[3])
                 : "r"(a[0]), "r"(a[1]), "r"(a[2]), "r"(a[3]), "r"(b0), "r"(b1));
}

// ---------------------------------------------------------------------------
// Fused pre-pass:
//   block 0           : init (zero marginal, mask detect/expand/sum)
//   blocks 1..1280    : convert+transpose W fp32 [K,N] -> bf16 [N,K]
//   blocks 1281..9472 : convert hidden fp32 -> bf16 (float4 granularity)
// ---------------------------------------------------------------------------
#define W_BLOCKS 1280                 // NN*KK / 256
#define A_BLOCKS 8192                 // MM*KK/4 / 256
#define PRE_GRID (1 + W_BLOCKS + A_BLOCKS)

__global__ void __launch_bounds__(1024) pre_kernel(const float* __restrict__ A,
                                                   const float* __restrict__ W,
                                                   const void* __restrict__ maskraw) {
    int bx = blockIdx.x;
    int tid = threadIdx.x;

    if (bx == 0) {
        if (tid < NN) g_marginal[tid] = 0.f;

        __shared__ int isU8;
        if (tid == 0) isU8 = 0;
        __syncthreads();

        const unsigned char* mb = (const unsigned char*)maskraw;
        int any = 0;
        for (int i = tid; i < MM; i += 1024)
            if ((i & 3) && mb[i]) any = 1;
        if (any) isU8 = 1;
        __syncthreads();

        bool u8 = (isU8 != 0);
        const int* mi = (const int*)maskraw;
        float local = 0.f;
        for (int i = tid; i < MM; i += 1024) {
            bool on = u8 ? (mb[i] != 0) : (mi[i] != 0);
            float v = on ? 1.f : 0.f;
            g_maskf[i] = v;
            local += v;
        }
        __shared__ float red[32];
        for (int o = 16; o; o >>= 1) local += __shfl_xor_sync(0xffffffffu, local, o);
        if ((tid & 31) == 0) red[tid >> 5] = local;
        __syncthreads();
        if (tid < 32) {
            float s = red[tid];
            for (int o = 16; o; o >>= 1) s += __shfl_xor_sync(0xffffffffu, s, o);
            if (tid == 0) g_msum = s;
        }
        return;
    }

    if (tid >= 256) return;   // convert sections use 256 threads

    if (bx <= W_BLOCKS) {
        int idx = (bx - 1) * 256 + tid;           // over N*K
        int n = idx / KK, k = idx % KK;
        g_Wh[idx] = __float2bfloat16(W[(size_t)k * NN + n]);
    } else {
        size_t i4 = (size_t)(bx - 1 - W_BLOCKS) * 256 + tid;   // float4 index
        float4 v = ((const float4*)A)[i4];
        __nv_bfloat162 h0, h1;
        h0.x = __float2bfloat16(v.x); h0.y = __float2bfloat16(v.y);
        h1.x = __float2bfloat16(v.z); h1.y = __float2bfloat16(v.w);
        ((uint2*)g_Ah)[i4] = make_uint2(*(uint32_t*)&h0, *(uint32_t*)&h1);
    }
}

// ---------------------------------------------------------------------------
// mma.sync bf16 GEMM: logits[M,N] = A[M,K] @ W[K,N] + bias
// CTA 128x128, 8 warps (64x32 each), BK=64, 3-stage cp.async ring,
// one __syncthreads per chunk (8 total), fp32 register accumulators.
// ---------------------------------------------------------------------------
#define BM 128
#define BN 128
#define BKC 64
#define SSTR 72                       // padded smem row stride (elements)
#define ROWB (SSTR * 2)               // 144 bytes per smem row
#define NCHUNK 8                      // K / BKC
#define STAGES 3
#define AB_OFF (BM * ROWB)            // 18432: B offset within a stage
#define STAGE_BYTES (2 * BM * ROWB)   // 36864 per stage (A + B)
#define GEMM_SMEM (STAGES * STAGE_BYTES)  // 110592

__global__ void __launch_bounds__(256, 2) mma_gemm_kernel(const float* __restrict__ bias) {
    extern __shared__ char smem[];
    uint32_t sbase = smem_u32(smem);

    int tid = threadIdx.x;
    int lane = tid & 31;
    int wid = tid >> 5;
    int wr = wid >> 2;                // 0..1  (warp row: 64 m each)
    int wc = wid & 3;                 // 0..3  (warp col: 32 n each)
    int m0 = blockIdx.y * BM;
    int n0 = blockIdx.x * BN;

    float acc[4][4][4];
#pragma unroll
    for (int i = 0; i < 4; i++)
#pragma unroll
        for (int j = 0; j < 4; j++)
#pragma unroll
            for (int r = 0; r < 4; r++) acc[i][j][r] = 0.f;

    // Per-thread load slots: 64 k = 8 x 16B segments per row;
    // thread covers rows tid/8 + 32p (p=0..3), segment tid%8.
    int rowA = tid >> 3, seg = tid & 7;

#define LOAD_CHUNK(kc, st) do {                                               \
        int koff = (kc) * BKC;                                                \
        uint32_t sb = sbase + (st) * STAGE_BYTES;                             \
        _Pragma("unroll")                                                     \
        for (int p = 0; p < 4; p++) {                                         \
            int r = rowA + 32 * p;                                            \
            cp_async16(sb + r * ROWB + seg * 16,                              \
                       g_Ah + (size_t)(m0 + r) * KK + koff + seg * 8);        \
            cp_async16(sb + AB_OFF + r * ROWB + seg * 16,                     \
                       g_Wh + (size_t)(n0 + r) * KK + koff + seg * 8);        \
        }                                                                     \
    } while (0)

    // Prologue: chunks 0,1 in flight
    LOAD_CHUNK(0, 0); asm volatile("cp.async.commit_group;");
    LOAD_CHUNK(1, 1); asm volatile("cp.async.commit_group;");

    // ldmatrix per-lane addresses (byte offsets within a stage)
    uint32_t aoff = (uint32_t)((wr * 64 + (lane & 15)) * ROWB + (lane >> 4) * 16);
    uint32_t boff = (uint32_t)(AB_OFF + (wc * 32 + (lane & 7) + ((lane >> 4) & 1) * 8) * ROWB
                               + ((lane >> 3) & 1) * 16);

    for (int kc = 0; kc < NCHUNK; kc++) {
        asm volatile("cp.async.wait_group 1;");   // chunk kc resident
        __syncthreads();

        // prefetch chunk kc+2 into stage (kc+2)%3 (its previous tenant kc-1
        // retired before this barrier). Always commit to keep numbering.
        if (kc + 2 < NCHUNK) LOAD_CHUNK(kc + 2, (kc + 2) % 3);
        asm volatile("cp.async.commit_group;");

        uint32_t stb = sbase + (kc % 3) * STAGE_BYTES;
        uint32_t aBase = stb + aoff;
        uint32_t bBase = stb + boff;
#pragma unroll
        for (int kk = 0; kk < 4; kk++) {
            uint32_t kb = kk * 32;  // 16 bf16 = 32 bytes
            uint32_t afr[4][4], bfr[2][4];
#pragma unroll
            for (int mi = 0; mi < 4; mi++)
                ldmatrix_x4(afr[mi], aBase + mi * 16 * ROWB + kb);
#pragma unroll
            for (int nj = 0; nj < 2; nj++)
                ldmatrix_x4(bfr[nj], bBase + nj * 16 * ROWB + kb);
#pragma unroll
            for (int mi = 0; mi < 4; mi++)
#pragma unroll
                for (int ni = 0; ni < 4; ni++) {
                    uint32_t b0 = bfr[ni >> 1][(ni & 1) * 2];
                    uint32_t b1 = bfr[ni >> 1][(ni & 1) * 2 + 1];
                    mma16816(acc[mi][ni], afr[mi], b0, b1);
                }
        }
    }

    // Epilogue: bias add + store
    int l4 = lane >> 2, l2 = (lane & 3) * 2;
    float2 bb[4];
#pragma unroll
    for (int ni = 0; ni < 4; ni++) {
        int col = n0 + wc * 32 + ni * 8 + l2;
        bb[ni].x = __ldg(&bias[col]);
        bb[ni].y = __ldg(&bias[col + 1]);
    }
#pragma unroll
    for (int mi = 0; mi < 4; mi++) {
        int row = m0 + wr * 64 + mi * 16 + l4;
#pragma unroll
        for (int ni = 0; ni < 4; ni++) {
            int col = n0 + wc * 32 + ni * 8 + l2;
            float2 v0 = make_float2(acc[mi][ni][0] + bb[ni].x, acc[mi][ni][1] + bb[ni].y);
            float2 v1 = make_float2(acc[mi][ni][2] + bb[ni].x, acc[mi][ni][3] + bb[ni].y);
            *(float2*)&g_logits[(size_t)row * NN + col] = v0;
            *(float2*)&g_logits[(size_t)(row + 8) * NN + col] = v1;
        }
    }
}

// ---------------------------------------------------------------------------
// Exact fp32 rescore of one candidate column (warp-cooperative)
// ---------------------------------------------------------------------------
__device__ __forceinline__ float exact_score(const float* __restrict__ hidden,
                                             const float* __restrict__ W,
                                             const float* __restrict__ bias,
                                             const float* __restrict__ grow,
                                             int n, int col, int v, int lane) {
    const float* hrow = hidden + (size_t)n * KK;
    float s = 0.f;
#pragma unroll 4
    for (int j = lane; j < KK; j += 32)
        s = fmaf(hrow[j], W[(size_t)j * NN + col], s);
    for (int o = 16; o; o >>= 1) s += __shfl_xor_sync(0xffffffffu, s, o);
    return s + bias[col] + grow[v];
}

// ---------------------------------------------------------------------------
// Row kernel: warp per (n, g). argmax(logits+gumbel); rows whose bf16-logit
// top-2 gap < 2e-2 get exact fp32 rescoring of all candidates within 2.4e-2.
// softmax(logits) masked -> marginal.
// ---------------------------------------------------------------------------
#define RESCORE_GAP  2.0e-2f
#define RESCORE_WIN  2.4e-2f

__global__ void __launch_bounds__(1024) row_kernel(const float* __restrict__ gumbels,
                                                   const float* __restrict__ cb,
                                                   float* __restrict__ out,
                                                   const float* __restrict__ hidden,
                                                   const float* __restrict__ W,
                                                   const float* __restrict__ bias) {
    __shared__ float smarg[NN];
    int tid = threadIdx.x;
    if (tid < NN) smarg[tid] = 0.f;
    __syncthreads();

    int warpid = tid >> 5;
    int lane = tid & 31;
    int w = blockIdx.x * 32 + warpid;   // flat row index n*G + g
    int n = w >> 1;
    int g = w & 1;

    const float* lrow = g_logits + (size_t)n * NN + g * VV;
    const float* grow = gumbels + (size_t)w * VV;

    float l[10], sc[10];
#pragma unroll
    for (int i = 0; i < 10; i++) {
        l[i] = lrow[lane + 32 * i];
        sc[i] = l[i] + grow[lane + 32 * i];
    }

    // argmax of logits + gumbels (first occurrence on ties)
    float best = -3.4e38f;
    int bidx = 0;
#pragma unroll
    for (int i = 0; i < 10; i++) {
        int v = lane + 32 * i;
        if (sc[i] > best) { best = sc[i]; bidx = v; }
    }
    for (int o = 16; o; o >>= 1) {
        float ob = __shfl_down_sync(0xffffffffu, best, o);
        int oi   = __shfl_down_sync(0xffffffffu, bidx, o);
        if (ob > best || (ob == best && oi < bidx)) { best = ob; bidx = oi; }
    }
    best = __shfl_sync(0xffffffffu, best, 0);
    bidx = __shfl_sync(0xffffffffu, bidx, 0);

    // second best (excluding bidx), for the near-tie test
    float sec = -3.4e38f;
#pragma unroll
    for (int i = 0; i < 10; i++) {
        int v = lane + 32 * i;
        if (v != bidx && sc[i] > sec) sec = sc[i];
    }
    for (int o = 16; o; o >>= 1) sec = fmaxf(sec, __shfl_xor_sync(0xffffffffu, sec, o));

    // near-tie: rescore all candidates within the window exactly in fp32
    if (best - sec < RESCORE_GAP) {
        float thr = best - RESCORE_WIN;
        float exbest = -3.4e38f;
        int exidx = VV;
        int col0 = g * VV;
#pragma unroll
        for (int i = 0; i < 10; i++) {
            unsigned mset = __ballot_sync(0xffffffffu, sc[i] >= thr);
            while (mset) {
                int src = __ffs(mset) - 1;
                mset &= mset - 1;
                int v = src + 32 * i;
                float ex = exact_score(hidden, W, bias, grow, n, col0 + v, v, lane);
                if (ex > exbest || (ex == exbest && v < exidx)) { exbest = ex; exidx = v; }
            }
        }
        bidx = exidx;
    }

    // softmax(logits) for marginal (no gumbel, no tau)
    float mx = l[0];
#pragma unroll
    for (int i = 1; i < 10; i++) mx = fmaxf(mx, l[i]);
    for (int o = 16; o; o >>= 1) mx = fmaxf(mx, __shfl_xor_sync(0xffffffffu, mx, o));
    float e[10];
    float sum = 0.f;
#pragma unroll
    for (int i = 0; i < 10; i++) { e[i] = __expf(l[i] - mx); sum += e[i]; }
    for (int o = 16; o; o >>= 1) sum += __shfl_xor_sync(0xffffffffu, sum, o);

    if (g_maskf[n] != 0.f) {
        float inv = 1.f / sum;
#pragma unroll
        for (int i = 0; i < 10; i++)
            atomicAdd(&smarg[g * VV + lane + 32 * i], e[i] * inv);
    }

    // codevector gather: 128 floats = 32 lanes x float4
    const float4* c4 = (const float4*)(cb + (size_t)(g * VV + bidx) * DG);
    float4* o4 = (float4*)(out + (size_t)n * 256 + g * DG);
    o4[lane] = c4[lane];

    __syncthreads();
    if (tid < NN) atomicAdd(&g_marginal[tid], smarg[tid]);
}

// ---------------------------------------------------------------------------
// Final: perplexity = sum_g exp(-sum_v p*log(p+eps)), p = marginal/msum
// ---------------------------------------------------------------------------
__global__ void __launch_bounds__(640) final_kernel(float* __restrict__ out, int out_size) {
    int tid = threadIdx.x;
    float msum = g_msum;
    float val = g_marginal[tid] / msum;
    float t = val * logf(val + 1e-7f);

    __shared__ float s[2];
    if (tid < 2) s[tid] = 0.f;
    __syncthreads();

    for (int o = 16; o; o >>= 1) t += __shfl_xor_sync(0xffffffffu, t, o);
    int warpid = tid >> 5;
    if ((tid & 31) == 0) atomicAdd(&s[warpid >= 10 ? 1 : 0], t);
    __syncthreads();

    if (tid == 0) out[out_size - 1] = expf(-s[0]) + expf(-s[1]);
}

// ---------------------------------------------------------------------------
extern "C" void kernel_launch(void* const* d_in, const int* in_sizes, int n_in,
                              void* d_out, int out_size) {
    const float* hidden = (const float*)d_in[0];   // [8,2048,512]
    const void*  mask   = d_in[1];                 // [8,2048]
    const float* W      = (const float*)d_in[2];   // [512,640]
    const float* b      = (const float*)d_in[3];   // [640]
    const float* cb     = (const float*)d_in[4];   // [1,640,128]
    const float* gum    = (const float*)d_in[5];   // [32768,320]
    float* out = (float*)d_out;

    cudaFuncSetAttribute(mma_gemm_kernel,
                         cudaFuncAttributeMaxDynamicSharedMemorySize, GEMM_SMEM);

    pre_kernel<<<PRE_GRID, 1024>>>(hidden, W, mask);

    dim3 ggrid(NN / BN, MM / BM);   // (5, 128)
    mma_gemm_kernel<<<ggrid, 256, GEMM_SMEM>>>(b);

    row_kernel<<<1024, 1024>>>(gum, cb, out, hidden, W, b);

    final_kernel<<<1, 640>>>(out, out_size);
}